// round 11
// baseline (speedup 1.0000x reference)
#include <cuda_runtime.h>
#include <math.h>

#define BB 64
#define CC 768
#define C2 1536
#define RR 96
#define EE 16

// ---- scratch (device globals) ----
__device__ float d_gT[CC * BB];        // pooled, [C][B]
__device__ float d_p1[4 * C2 * BB];    // gemm1 partials (4 slabs)
__device__ float d_h1T[C2 * BB];       // conv1+BN+GELU, [2C][B]
__device__ float d_pa[8 * RR * BB];    // ca1 partials (8 slabs)
__device__ float d_h2T[C2 * BB];       // gated, [2C][B]
__device__ float d_p2[8 * CC * BB];    // gemm2 partials (8 slabs)

__device__ __forceinline__ float gelu_exact(float z) {
    return 0.5f * z * (1.0f + erff(z * 0.7071067811865476f));
}
__device__ __forceinline__ float sig2(float z) {
    return 1.0f / (1.0f + expf(-2.0f * z));
}
__device__ __forceinline__ float4 unpack2(unsigned long long lo,
                                          unsigned long long hi) {
    float4 r;
    asm("mov.b64 {%0, %1}, %2;" : "=f"(r.x), "=f"(r.y) : "l"(lo));
    asm("mov.b64 {%0, %1}, %2;" : "=f"(r.z), "=f"(r.w) : "l"(hi));
    return r;
}

// ---- K0: global average pool, x[B,C,H,W] -> gT[C][B] ----
__global__ __launch_bounds__(256) void pool_kernel(const float4* __restrict__ x,
                                                   int nb) {
    int warp = blockIdx.x * 8 + (threadIdx.x >> 5);
    int lane = threadIdx.x & 31;
    for (int r = warp; r < BB * CC; r += nb * 8) {
        const float4* p = x + (size_t)r * 256 + lane;
        float s = 0.f;
#pragma unroll
        for (int k = 0; k < 8; k++) {
            float4 v = p[32 * k];
            s += (v.x + v.y) + (v.z + v.w);
        }
#pragma unroll
        for (int o = 16; o; o >>= 1) s += __shfl_xor_sync(0xffffffffu, s, o);
        if (lane == 0) {
            int b = r / CC, c = r - b * CC;
            d_gT[c * BB + b] = s * (1.0f / 1024.0f);
        }
    }
}

// packed-FMA body for one 32-k chunk, thread tile 4b x TJ j
template<int TJ>
__device__ __forceinline__ void mm_body32(const float* sa, const float* sw,
                                          int bg, int jg,
                                          unsigned long long* acc) {
    const float* aw = sw + (jg * TJ) * 36;
#pragma unroll 4
    for (int k4 = 0; k4 < 8; k4++) {
        float4 wv[TJ];
#pragma unroll
        for (int q = 0; q < TJ; q++)
            wv[q] = *(const float4*)(aw + q * 36 + k4 * 4);
#pragma unroll
        for (int u = 0; u < 4; u++) {
            ulonglong2 av =
                *(const ulonglong2*)(sa + (k4 * 4 + u) * BB + bg * 4);
#pragma unroll
            for (int q = 0; q < TJ; q++) {
                float w = (u == 0) ? wv[q].x : (u == 1) ? wv[q].y
                        : (u == 2) ? wv[q].z : wv[q].w;
                unsigned long long ww;
                asm("mov.b64 %0, {%1, %1};" : "=l"(ww) : "f"(w));
                asm("fma.rn.f32x2 %0, %1, %2, %0;"
                    : "+l"(acc[q * 2 + 0]) : "l"(av.x), "l"(ww));
                asm("fma.rn.f32x2 %0, %1, %2, %0;"
                    : "+l"(acc[q * 2 + 1]) : "l"(av.y), "l"(ww));
            }
        }
    }
}

// double-buffered pipelined GEMM: NCH chunks of 32 k, thread tile 4b x TJ j
template<int TJ, int NCH>
__device__ __forceinline__ void tile_mm_pipe(
    const float* __restrict__ W, int ldw,
    const float* __restrict__ actT,
    int j0, int k0,
    unsigned long long* acc, float* s_act, float* s_w) {
    constexpr int JT  = 16 * TJ;
    constexpr int WPT = JT * 8 / 256;
    const int tid = threadIdx.x;
    const int bg = tid % 16, jg = tid / 16;
    float4 a_reg[2], w_reg[WPT];
    {
        const float4* a4 = (const float4*)(actT + k0 * BB);
#pragma unroll
        for (int i = 0; i < 2; i++) a_reg[i] = a4[tid + 256 * i];
#pragma unroll
        for (int i = 0; i < WPT; i++) {
            int f = tid + 256 * i;
            int j = f >> 3, kq = f & 7;
            w_reg[i] = *(const float4*)(W + (size_t)(j0 + j) * ldw + k0 + kq * 4);
        }
    }
#pragma unroll
    for (int c = 0; c < NCH; c++) {
        float* sa = s_act + (c & 1) * (32 * BB);
        float* sw = s_w + (c & 1) * (JT * 36);
#pragma unroll
        for (int i = 0; i < 2; i++) ((float4*)sa)[tid + 256 * i] = a_reg[i];
#pragma unroll
        for (int i = 0; i < WPT; i++) {
            int f = tid + 256 * i;
            int j = f >> 3, kq = f & 7;
            *(float4*)(sw + j * 36 + kq * 4) = w_reg[i];
        }
        if (c + 1 < NCH) {
            int kk = k0 + (c + 1) * 32;
            const float4* a4 = (const float4*)(actT + kk * BB);
#pragma unroll
            for (int i = 0; i < 2; i++) a_reg[i] = a4[tid + 256 * i];
#pragma unroll
            for (int i = 0; i < WPT; i++) {
                int f = tid + 256 * i;
                int j = f >> 3, kq = f & 7;
                w_reg[i] = *(const float4*)(W + (size_t)(j0 + j) * ldw + kk + kq * 4);
            }
        }
        __syncthreads();
        mm_body32<TJ>(sa, sw, bg, jg, acc);
        __syncthreads();
    }
}

// ---- K1: gemm1 partials. grid 192 = 48 jt x 4 ks (K-slice 192) ----
__global__ __launch_bounds__(256) void gemm1_kernel(const float* __restrict__ w1) {
    __shared__ float s_act[2 * 32 * BB];
    __shared__ float s_w[2 * 32 * 36];
    int jt = blockIdx.x % 48, ks = blockIdx.x / 48;
    const int bg = threadIdx.x % 16, jg = threadIdx.x / 16;
    unsigned long long acc[4] = {};
    tile_mm_pipe<2, 6>(w1, CC, d_gT, jt * 32, ks * 192, acc, s_act, s_w);
#pragma unroll
    for (int q = 0; q < 2; q++) {
        int j = jt * 32 + jg * 2 + q;
        *(float4*)(d_p1 + (ks * C2 + j) * BB + bg * 4) =
            unpack2(acc[q * 2 + 0], acc[q * 2 + 1]);
    }
}

// ---- K2: reduce 4 slabs + BN + GELU -> h1T. grid 96 ----
__global__ __launch_bounds__(256) void red1_kernel(
    const float* __restrict__ b1,
    const float* __restrict__ bg_, const float* __restrict__ bb_,
    const float* __restrict__ bm_, const float* __restrict__ bv_) {
    int v = blockIdx.x * 256 + threadIdx.x;   // 24576 float4 total
    float4 s = {0.f, 0.f, 0.f, 0.f};
#pragma unroll
    for (int k = 0; k < 4; k++) {
        float4 p = *((const float4*)d_p1 + k * (C2 * BB / 4) + v);
        s.x += p.x; s.y += p.y; s.z += p.z; s.w += p.w;
    }
    int j = v >> 4;
    float sc = rsqrtf(bv_[j] + 1e-5f) * bg_[j];
    float sh = bb_[j] + (b1[j] - bm_[j]) * sc;
    s.x = gelu_exact(s.x * sc + sh);
    s.y = gelu_exact(s.y * sc + sh);
    s.z = gelu_exact(s.z * sc + sh);
    s.w = gelu_exact(s.w * sc + sh);
    *((float4*)d_h1T + v) = s;
}

// ---- K3: ca1 partials. grid 24 = 3 jt x 8 ks (K-slice 192) ----
__global__ __launch_bounds__(256) void ca1_kernel(const float* __restrict__ caw1) {
    __shared__ float s_act[2 * 32 * BB];
    __shared__ float s_w[2 * 32 * 36];
    int jt = blockIdx.x % 3, ks = blockIdx.x / 3;
    const int bg = threadIdx.x % 16, jg = threadIdx.x / 16;
    unsigned long long acc[4] = {};
    tile_mm_pipe<2, 6>(caw1, C2, d_h1T, jt * 32, ks * 192, acc, s_act, s_w);
#pragma unroll
    for (int q = 0; q < 2; q++) {
        int j = jt * 32 + jg * 2 + q;
        *(float4*)(d_pa + (ks * RR + j) * BB + bg * 4) =
            unpack2(acc[q * 2 + 0], acc[q * 2 + 1]);
    }
}

// ---- K4: fused [reduce pa -> aT in smem] + ca2(K=96) + gating -> h2T ----
// grid 24 (j-tile 64 over C2). dynamic smem: aT_s[96*64] + w[64*100]
__global__ __launch_bounds__(256) void ca2_kernel(
    const float* __restrict__ cab1,
    const float* __restrict__ caw2, const float* __restrict__ cab2) {
    extern __shared__ float smem[];
    float* s_act = smem;               // 96*64
    float* s_w   = smem + 96 * 64;     // 64*100
    const int tid = threadIdx.x;
    const int j0 = blockIdx.x * 64;
    const int bg = tid % 16, jg = tid / 16;
    // phase A: reduce 8 slabs + bias + GELU -> s_act (aT layout [96][64])
    for (int i = tid; i < RR * BB / 4; i += 256) {
        float4 s = {0.f, 0.f, 0.f, 0.f};
#pragma unroll
        for (int k = 0; k < 8; k++) {
            float4 p = *((const float4*)d_pa + k * (RR * BB / 4) + i);
            s.x += p.x; s.y += p.y; s.z += p.z; s.w += p.w;
        }
        float bs = cab1[i >> 4];
        s.x = gelu_exact(s.x + bs);
        s.y = gelu_exact(s.y + bs);
        s.z = gelu_exact(s.z + bs);
        s.w = gelu_exact(s.w + bs);
        ((float4*)s_act)[i] = s;
    }
    // phase A2: weight tile caw2[j0..j0+64][96], pitch 100
    {
        const float4* w4g = (const float4*)caw2;
        for (int f = tid; f < 64 * 24; f += 256) {
            int j = f / 24, kq = f % 24;
            float4 v = w4g[(size_t)(j0 + j) * 24 + kq];
            *(float4*)(s_w + j * 100 + kq * 4) = v;
        }
    }
    __syncthreads();
    // phase B: K=96 GEMM, thread tile 4b x 4j
    unsigned long long acc[8] = {};
#pragma unroll 4
    for (int k = 0; k < 96; k++) {
        ulonglong2 av = *(const ulonglong2*)(s_act + k * BB + bg * 4);
#pragma unroll
        for (int q = 0; q < 4; q++) {
            float w = s_w[(jg * 4 + q) * 100 + k];
            unsigned long long ww;
            asm("mov.b64 %0, {%1, %1};" : "=l"(ww) : "f"(w));
            asm("fma.rn.f32x2 %0, %1, %2, %0;"
                : "+l"(acc[q * 2 + 0]) : "l"(av.x), "l"(ww));
            asm("fma.rn.f32x2 %0, %1, %2, %0;"
                : "+l"(acc[q * 2 + 1]) : "l"(av.y), "l"(ww));
        }
    }
    // epilogue: gating
#pragma unroll
    for (int q = 0; q < 4; q++) {
        int j = j0 + jg * 4 + q;
        float bias = cab2[j];
        float4 z = unpack2(acc[q * 2 + 0], acc[q * 2 + 1]);
        float4 h = *(const float4*)(d_h1T + j * BB + bg * 4);
        float4 o;
        o.x = h.x * sig2(z.x + bias);
        o.y = h.y * sig2(z.y + bias);
        o.z = h.z * sig2(z.z + bias);
        o.w = h.w * sig2(z.w + bias);
        *(float4*)(d_h2T + j * BB + bg * 4) = o;
    }
}

// ---- K5: gemm2 partials. grid 192 = 24 jt x 8 ks (K-slice 192) ----
__global__ __launch_bounds__(256) void gemm2_kernel(const float* __restrict__ w2) {
    __shared__ float s_act[2 * 32 * BB];
    __shared__ float s_w[2 * 32 * 36];
    int jt = blockIdx.x % 24, ks = blockIdx.x / 24;
    const int bg = threadIdx.x % 16, jg = threadIdx.x / 16;
    unsigned long long acc[4] = {};
    tile_mm_pipe<2, 6>(w2, C2, d_h2T, jt * 32, ks * 192, acc, s_act, s_w);
#pragma unroll
    for (int q = 0; q < 2; q++) {
        int j = jt * 32 + jg * 2 + q;
        *(float4*)(d_p2 + (ks * CC + j) * BB + bg * 4) =
            unpack2(acc[q * 2 + 0], acc[q * 2 + 1]);
    }
}

// ---- K6: fused [reduce p2 + BN + GELU -> h3 row] + scores + top2 ----
// grid 64 (one block per batch row)
__global__ __launch_bounds__(256) void scores_kernel(
    const float* __restrict__ b2,
    const float* __restrict__ bg_, const float* __restrict__ bb_,
    const float* __restrict__ bm_, const float* __restrict__ bv_,
    const float* __restrict__ w3, const float* __restrict__ b3,
    float* __restrict__ out) {
    __shared__ float h3s[CC];
    __shared__ float sc[EE];
    const int tid = threadIdx.x;
    const int b = blockIdx.x;
    // phase A: h3 row = reduce 8 slabs + BN + GELU (uncoalesced but small)
    for (int j = tid; j < CC; j += 256) {
        float s = 0.f;
#pragma unroll
        for (int k = 0; k < 8; k++) s += d_p2[(k * CC + j) * BB + b];
        float scale = rsqrtf(bv_[j] + 1e-5f) * bg_[j];
        float shift = bb_[j] + (b2[j] - bm_[j]) * scale;
        h3s[j] = gelu_exact(s * scale + shift);
    }
    __syncthreads();
    // phase B: 16 expert dots (each warp does 2)
    int w = tid >> 5, lane = tid & 31;
#pragma unroll
    for (int q = 0; q < 2; q++) {
        int e = w + 8 * q;
        const float* wr = w3 + e * CC;
        float s = 0.f;
#pragma unroll
        for (int i = 0; i < CC / 32; i++) {
            int k = lane + 32 * i;
            s = fmaf(h3s[k], wr[k], s);
        }
#pragma unroll
        for (int o = 16; o; o >>= 1) s += __shfl_xor_sync(0xffffffffu, s, o);
        if (lane == 0) sc[e] = s + b3[e];
    }
    __syncthreads();
    if (tid == 0) {
        int i0 = 0; float v0 = sc[0];
#pragma unroll
        for (int t = 1; t < EE; t++) { if (sc[t] > v0) { v0 = sc[t]; i0 = t; } }
        int i1 = -1; float v1 = -3.402823466e38f;
#pragma unroll
        for (int t = 0; t < EE; t++) {
            if (t != i0 && sc[t] > v1) { v1 = sc[t]; i1 = t; }
        }
        float e1  = expf((v1 - v0) * 0.5f);
        float inv = 1.0f / (1.0f + e1);
        out[b * 2 + 0]       = (float)i0;
        out[b * 2 + 1]       = (float)i1;
        out[128 + b * 2 + 0] = inv;
        out[128 + b * 2 + 1] = e1 * inv;
    }
}

extern "C" void kernel_launch(void* const* d_in, const int* in_sizes, int n_in,
                              void* d_out, int out_size) {
    const float* x     = (const float*)d_in[0];
    const float* w1    = (const float*)d_in[1];
    const float* b1    = (const float*)d_in[2];
    const float* bn1_g = (const float*)d_in[3];
    const float* bn1_b = (const float*)d_in[4];
    const float* bn1_m = (const float*)d_in[5];
    const float* bn1_v = (const float*)d_in[6];
    const float* caw1  = (const float*)d_in[7];
    const float* cab1  = (const float*)d_in[8];
    const float* caw2  = (const float*)d_in[9];
    const float* cab2  = (const float*)d_in[10];
    const float* w2    = (const float*)d_in[11];
    const float* b2    = (const float*)d_in[12];
    const float* bn2_g = (const float*)d_in[13];
    const float* bn2_b = (const float*)d_in[14];
    const float* bn2_m = (const float*)d_in[15];
    const float* bn2_v = (const float*)d_in[16];
    const float* w3    = (const float*)d_in[17];
    const float* b3    = (const float*)d_in[18];

    int nsm = 148;
    cudaDeviceGetAttribute(&nsm, cudaDevAttrMultiProcessorCount, 0);
    int nb = 4 * nsm;

    static bool attr_done = false;
    if (!attr_done) {
        cudaFuncSetAttribute(ca2_kernel,
                             cudaFuncAttributeMaxDynamicSharedMemorySize,
                             (96 * 64 + 64 * 100) * (int)sizeof(float));
        attr_done = true;
    }

    pool_kernel<<<nb, 256>>>((const float4*)x, nb);
    gemm1_kernel<<<192, 256>>>(w1);
    red1_kernel<<<96, 256>>>(b1, bn1_g, bn1_b, bn1_m, bn1_v);
    ca1_kernel<<<24, 256>>>(caw1);
    ca2_kernel<<<24, 256, (96 * 64 + 64 * 100) * sizeof(float)>>>(cab1, caw2, cab2);
    gemm2_kernel<<<192, 256>>>(w2);
    scores_kernel<<<64, 256>>>(b2, bn2_g, bn2_b, bn2_m, bn2_v, w3, b3,
                               (float*)d_out);
}

// round 12
// speedup vs baseline: 1.2051x; 1.2051x over previous
#include <cuda_runtime.h>
#include <math.h>

#define BB 64
#define CC 768
#define C2 1536
#define RR 96
#define EE 16

// ---- scratch (device globals) ----
__device__ float d_gT[CC * BB];         // pooled, [C][B]
__device__ float d_p1[24 * C2 * BB];    // gemm1 partials (24 slabs)
__device__ float d_h1T[C2 * BB];        // conv1+BN+GELU, [2C][B]
__device__ float d_pa[48 * RR * BB];    // ca1 partials (48 slabs)
__device__ float d_aT[RR * BB];         // bottleneck, [R][B]
__device__ float d_h2T[C2 * BB];        // gated, [2C][B]
__device__ float d_p2[48 * CC * BB];    // gemm2 partials (48 slabs)
__device__ float d_h3[BB * CC];         // conv2+BN+GELU, [B][C]

__device__ __forceinline__ float gelu_exact(float z) {
    return 0.5f * z * (1.0f + erff(z * 0.7071067811865476f));
}
__device__ __forceinline__ float sig2(float z) {
    return 1.0f / (1.0f + expf(-2.0f * z));
}
__device__ __forceinline__ float4 unpack2(unsigned long long lo,
                                          unsigned long long hi) {
    float4 r;
    asm("mov.b64 {%0, %1}, %2;" : "=f"(r.x), "=f"(r.y) : "l"(lo));
    asm("mov.b64 {%0, %1}, %2;" : "=f"(r.z), "=f"(r.w) : "l"(hi));
    return r;
}

// ---- K0: global average pool, x[B,C,H,W] -> gT[C][B] ----
__global__ __launch_bounds__(256) void pool_kernel(const float4* __restrict__ x,
                                                   int nb) {
    int warp = blockIdx.x * 8 + (threadIdx.x >> 5);
    int lane = threadIdx.x & 31;
    for (int r = warp; r < BB * CC; r += nb * 8) {
        const float4* p = x + (size_t)r * 256 + lane;
        float s = 0.f;
#pragma unroll
        for (int k = 0; k < 8; k++) {
            float4 v = p[32 * k];
            s += (v.x + v.y) + (v.z + v.w);
        }
#pragma unroll
        for (int o = 16; o; o >>= 1) s += __shfl_xor_sync(0xffffffffu, s, o);
        if (lane == 0) {
            int b = r / CC, c = r - b * CC;
            d_gT[c * BB + b] = s * (1.0f / 1024.0f);
        }
    }
}

// single-chunk GEMM: KC=32 k-range, thread tile 4b x TJ j, JT = 16*TJ.
// s_act[32*64], s_w[JT*36]. acc = 2*TJ packed f32x2.
template<int TJ>
__device__ __forceinline__ void tile_mm32(
    const float* __restrict__ W, int ldw,
    const float* __restrict__ actT,
    int j0, int k0,
    unsigned long long* acc, float* s_act, float* s_w) {
    constexpr int JT = 16 * TJ;
    const int tid = threadIdx.x;
    const int bg = tid % 16, jg = tid / 16;
    {
        const float4* a4 = (const float4*)(actT + k0 * BB);
#pragma unroll
        for (int i = 0; i < 2; i++) ((float4*)s_act)[tid + 256 * i] = a4[tid + 256 * i];
        // weight tile JT x 32, pitch 36
        for (int f = tid; f < JT * 8; f += 256) {
            int j = f >> 3, kq = f & 7;
            float4 v = *(const float4*)(W + (size_t)(j0 + j) * ldw + k0 + kq * 4);
            *(float4*)(s_w + j * 36 + kq * 4) = v;
        }
    }
    __syncthreads();
    const float* aw = s_w + (jg * TJ) * 36;
#pragma unroll 4
    for (int k4 = 0; k4 < 8; k4++) {
        float4 wv[TJ];
#pragma unroll
        for (int q = 0; q < TJ; q++)
            wv[q] = *(const float4*)(aw + q * 36 + k4 * 4);
#pragma unroll
        for (int u = 0; u < 4; u++) {
            ulonglong2 av =
                *(const ulonglong2*)(s_act + (k4 * 4 + u) * BB + bg * 4);
#pragma unroll
            for (int q = 0; q < TJ; q++) {
                float w = (u == 0) ? wv[q].x : (u == 1) ? wv[q].y
                        : (u == 2) ? wv[q].z : wv[q].w;
                unsigned long long ww;
                asm("mov.b64 %0, {%1, %1};" : "=l"(ww) : "f"(w));
                asm("fma.rn.f32x2 %0, %1, %2, %0;"
                    : "+l"(acc[q * 2 + 0]) : "l"(av.x), "l"(ww));
                asm("fma.rn.f32x2 %0, %1, %2, %0;"
                    : "+l"(acc[q * 2 + 1]) : "l"(av.y), "l"(ww));
            }
        }
    }
}

// ---- K1: gemm1 partials. grid 576 = 24 jt (JT=64) x 24 ks (KC=32) ----
__global__ __launch_bounds__(256) void gemm1_kernel(const float* __restrict__ w1) {
    __shared__ float s_act[32 * BB];
    __shared__ float s_w[64 * 36];
    int jt = blockIdx.x % 24, ks = blockIdx.x / 24;
    const int bg = threadIdx.x % 16, jg = threadIdx.x / 16;
    unsigned long long acc[8] = {};
    tile_mm32<4>(w1, CC, d_gT, jt * 64, ks * 32, acc, s_act, s_w);
#pragma unroll
    for (int q = 0; q < 4; q++) {
        int j = jt * 64 + jg * 4 + q;
        *(float4*)(d_p1 + (ks * C2 + j) * BB + bg * 4) =
            unpack2(acc[q * 2 + 0], acc[q * 2 + 1]);
    }
}

// ---- K2: reduce 24 slabs + BN + GELU -> h1T. grid 96 ----
__global__ __launch_bounds__(256) void red1_kernel(
    const float* __restrict__ b1,
    const float* __restrict__ bg_, const float* __restrict__ bb_,
    const float* __restrict__ bm_, const float* __restrict__ bv_) {
    int v = blockIdx.x * 256 + threadIdx.x;   // 24576 float4
    float4 s = {0.f, 0.f, 0.f, 0.f};
#pragma unroll
    for (int k = 0; k < 24; k++) {
        float4 p = *((const float4*)d_p1 + k * (C2 * BB / 4) + v);
        s.x += p.x; s.y += p.y; s.z += p.z; s.w += p.w;
    }
    int j = v >> 4;
    float sc = rsqrtf(bv_[j] + 1e-5f) * bg_[j];
    float sh = bb_[j] + (b1[j] - bm_[j]) * sc;
    s.x = gelu_exact(s.x * sc + sh);
    s.y = gelu_exact(s.y * sc + sh);
    s.z = gelu_exact(s.z * sc + sh);
    s.w = gelu_exact(s.w * sc + sh);
    *((float4*)d_h1T + v) = s;
}

// ---- K3: ca1 partials. grid 144 = 3 jt (JT=32) x 48 ks (KC=32) ----
__global__ __launch_bounds__(256) void ca1_kernel(const float* __restrict__ caw1) {
    __shared__ float s_act[32 * BB];
    __shared__ float s_w[32 * 36];
    int jt = blockIdx.x % 3, ks = blockIdx.x / 3;
    const int bg = threadIdx.x % 16, jg = threadIdx.x / 16;
    unsigned long long acc[4] = {};
    tile_mm32<2>(caw1, C2, d_h1T, jt * 32, ks * 32, acc, s_act, s_w);
#pragma unroll
    for (int q = 0; q < 2; q++) {
        int j = jt * 32 + jg * 2 + q;
        *(float4*)(d_pa + (ks * RR + j) * BB + bg * 4) =
            unpack2(acc[q * 2 + 0], acc[q * 2 + 1]);
    }
}

// ---- K4: reduce 48 slabs + bias + GELU -> aT. grid 6 ----
__global__ __launch_bounds__(256) void reda_kernel(const float* __restrict__ cab1) {
    int v = blockIdx.x * 256 + threadIdx.x;   // 1536 float4
    float4 s = {0.f, 0.f, 0.f, 0.f};
#pragma unroll
    for (int k = 0; k < 48; k++) {
        float4 p = *((const float4*)d_pa + k * (RR * BB / 4) + v);
        s.x += p.x; s.y += p.y; s.z += p.z; s.w += p.w;
    }
    float bs = cab1[v >> 4];
    s.x = gelu_exact(s.x + bs);
    s.y = gelu_exact(s.y + bs);
    s.z = gelu_exact(s.z + bs);
    s.w = gelu_exact(s.w + bs);
    *((float4*)d_aT + v) = s;
}

// ---- K5: ca2 (K=96) + gating -> h2T. grid 96 (JT=16) ----
__global__ __launch_bounds__(256) void ca2_kernel(
    const float* __restrict__ caw2, const float* __restrict__ cab2) {
    __shared__ float s_act[96 * BB];   // 24 KB
    __shared__ float s_w[16 * 100];
    const int tid = threadIdx.x;
    const int j0 = blockIdx.x * 16;
    const int bg = tid % 16, jg = tid / 16;
    {
        const float4* a4 = (const float4*)d_aT;
        for (int i = tid; i < 96 * 16; i += 256) ((float4*)s_act)[i] = a4[i];
        const float4* w4g = (const float4*)caw2;
        for (int f = tid; f < 16 * 24; f += 256) {
            int j = f / 24, kq = f % 24;
            float4 v = w4g[(size_t)(j0 + j) * 24 + kq];
            *(float4*)(s_w + j * 100 + kq * 4) = v;
        }
    }
    __syncthreads();
    unsigned long long acc[2] = {};
    const float* aw = s_w + jg * 100;
#pragma unroll 4
    for (int k = 0; k < 96; k++) {
        ulonglong2 av = *(const ulonglong2*)(s_act + k * BB + bg * 4);
        float w = aw[k];
        unsigned long long ww;
        asm("mov.b64 %0, {%1, %1};" : "=l"(ww) : "f"(w));
        asm("fma.rn.f32x2 %0, %1, %2, %0;" : "+l"(acc[0]) : "l"(av.x), "l"(ww));
        asm("fma.rn.f32x2 %0, %1, %2, %0;" : "+l"(acc[1]) : "l"(av.y), "l"(ww));
    }
    int j = j0 + jg;
    float bias = cab2[j];
    float4 z = unpack2(acc[0], acc[1]);
    float4 h = *(const float4*)(d_h1T + j * BB + bg * 4);
    float4 o;
    o.x = h.x * sig2(z.x + bias);
    o.y = h.y * sig2(z.y + bias);
    o.z = h.z * sig2(z.z + bias);
    o.w = h.w * sig2(z.w + bias);
    *(float4*)(d_h2T + j * BB + bg * 4) = o;
}

// ---- K6: gemm2 partials. grid 576 = 12 jt (JT=64) x 48 ks (KC=32) ----
__global__ __launch_bounds__(256) void gemm2_kernel(const float* __restrict__ w2) {
    __shared__ float s_act[32 * BB];
    __shared__ float s_w[64 * 36];
    int jt = blockIdx.x % 12, ks = blockIdx.x / 12;
    const int bg = threadIdx.x % 16, jg = threadIdx.x / 16;
    unsigned long long acc[8] = {};
    tile_mm32<4>(w2, C2, d_h2T, jt * 64, ks * 32, acc, s_act, s_w);
#pragma unroll
    for (int q = 0; q < 4; q++) {
        int j = jt * 64 + jg * 4 + q;
        *(float4*)(d_p2 + (ks * CC + j) * BB + bg * 4) =
            unpack2(acc[q * 2 + 0], acc[q * 2 + 1]);
    }
}

// ---- K7: reduce 48 slabs + BN + GELU -> h3 [B][C]. grid 48 ----
__global__ __launch_bounds__(256) void red2_kernel(
    const float* __restrict__ b2,
    const float* __restrict__ bg_, const float* __restrict__ bb_,
    const float* __restrict__ bm_, const float* __restrict__ bv_) {
    int v = blockIdx.x * 256 + threadIdx.x;   // 12288 float4
    float4 s = {0.f, 0.f, 0.f, 0.f};
#pragma unroll
    for (int k = 0; k < 48; k++) {
        float4 p = *((const float4*)d_p2 + k * (CC * BB / 4) + v);
        s.x += p.x; s.y += p.y; s.z += p.z; s.w += p.w;
    }
    int j = v >> 4, b0 = (v & 15) * 4;
    float sc = rsqrtf(bv_[j] + 1e-5f) * bg_[j];
    float sh = bb_[j] + (b2[j] - bm_[j]) * sc;
    d_h3[(b0 + 0) * CC + j] = gelu_exact(s.x * sc + sh);
    d_h3[(b0 + 1) * CC + j] = gelu_exact(s.y * sc + sh);
    d_h3[(b0 + 2) * CC + j] = gelu_exact(s.z * sc + sh);
    d_h3[(b0 + 3) * CC + j] = gelu_exact(s.w * sc + sh);
}

// ---- K8: scores + top-2 + softmax. grid 64 ----
__global__ __launch_bounds__(512) void scores_kernel(
    const float* __restrict__ w3, const float* __restrict__ b3,
    float* __restrict__ out) {
    __shared__ float sc[EE];
    const int b = blockIdx.x;
    int e    = threadIdx.x >> 5;
    int lane = threadIdx.x & 31;
    const float* h = d_h3 + b * CC;
    const float* wr = w3 + e * CC;
    float s = 0.f;
#pragma unroll
    for (int i = 0; i < CC / 32; i++) {
        int k = lane + 32 * i;
        s = fmaf(h[k], wr[k], s);
    }
#pragma unroll
    for (int o = 16; o; o >>= 1) s += __shfl_xor_sync(0xffffffffu, s, o);
    if (lane == 0) sc[e] = s + b3[e];
    __syncthreads();
    if (threadIdx.x == 0) {
        int i0 = 0; float v0 = sc[0];
#pragma unroll
        for (int t = 1; t < EE; t++) { if (sc[t] > v0) { v0 = sc[t]; i0 = t; } }
        int i1 = -1; float v1 = -3.402823466e38f;
#pragma unroll
        for (int t = 0; t < EE; t++) {
            if (t != i0 && sc[t] > v1) { v1 = sc[t]; i1 = t; }
        }
        float e1  = expf((v1 - v0) * 0.5f);
        float inv = 1.0f / (1.0f + e1);
        out[b * 2 + 0]       = (float)i0;
        out[b * 2 + 1]       = (float)i1;
        out[128 + b * 2 + 0] = inv;
        out[128 + b * 2 + 1] = e1 * inv;
    }
}

extern "C" void kernel_launch(void* const* d_in, const int* in_sizes, int n_in,
                              void* d_out, int out_size) {
    const float* x     = (const float*)d_in[0];
    const float* w1    = (const float*)d_in[1];
    const float* b1    = (const float*)d_in[2];
    const float* bn1_g = (const float*)d_in[3];
    const float* bn1_b = (const float*)d_in[4];
    const float* bn1_m = (const float*)d_in[5];
    const float* bn1_v = (const float*)d_in[6];
    const float* caw1  = (const float*)d_in[7];
    const float* cab1  = (const float*)d_in[8];
    const float* caw2  = (const float*)d_in[9];
    const float* cab2  = (const float*)d_in[10];
    const float* w2    = (const float*)d_in[11];
    const float* b2    = (const float*)d_in[12];
    const float* bn2_g = (const float*)d_in[13];
    const float* bn2_b = (const float*)d_in[14];
    const float* bn2_m = (const float*)d_in[15];
    const float* bn2_v = (const float*)d_in[16];
    const float* w3    = (const float*)d_in[17];
    const float* b3    = (const float*)d_in[18];

    int nsm = 148;
    cudaDeviceGetAttribute(&nsm, cudaDevAttrMultiProcessorCount, 0);
    int nb = 4 * nsm;

    pool_kernel<<<nb, 256>>>((const float4*)x, nb);
    gemm1_kernel<<<576, 256>>>(w1);
    red1_kernel<<<96, 256>>>(b1, bn1_g, bn1_b, bn1_m, bn1_v);
    ca1_kernel<<<144, 256>>>(caw1);
    reda_kernel<<<6, 256>>>(cab1);
    ca2_kernel<<<96, 256>>>(caw2, cab2);
    gemm2_kernel<<<576, 256>>>(w2);
    red2_kernel<<<48, 256>>>(b2, bn2_g, bn2_b, bn2_m, bn2_v);
    scores_kernel<<<64, 512>>>(w3, b3, (float*)d_out);
}

// round 13
// speedup vs baseline: 1.4552x; 1.2075x over previous
#include <cuda_runtime.h>
#include <math.h>

#define BB 64
#define CC 768
#define C2 1536
#define RR 96
#define EE 16

// ---- scratch (device globals) ----
__device__ float d_gT[CC * BB];      // pooled, [C][B]
__device__ float d_h1pre[C2 * BB];   // gemm1 accumulation (pre-BN), [2C][B]
__device__ float d_apre[RR * BB];    // ca1 accumulation (pre-GELU), [R][B]
__device__ float d_h2T[C2 * BB];     // gated, [2C][B]
__device__ float d_h3pre[CC * BB];   // gemm2 accumulation (pre-BN), [C][B]

__device__ __forceinline__ float gelu_exact(float z) {
    return 0.5f * z * (1.0f + erff(z * 0.7071067811865476f));
}
__device__ __forceinline__ float sig2(float z) {
    return 1.0f / (1.0f + expf(-2.0f * z));
}
__device__ __forceinline__ float4 unpack2(unsigned long long lo,
                                          unsigned long long hi) {
    float4 r;
    asm("mov.b64 {%0, %1}, %2;" : "=f"(r.x), "=f"(r.y) : "l"(lo));
    asm("mov.b64 {%0, %1}, %2;" : "=f"(r.z), "=f"(r.w) : "l"(hi));
    return r;
}
__device__ __forceinline__ void red_add4(float* p, float4 v) {
    asm volatile("red.global.add.v4.f32 [%0], {%1, %2, %3, %4};"
                 :: "l"(p), "f"(v.x), "f"(v.y), "f"(v.z), "f"(v.w)
                 : "memory");
}

// ---- K0: pool (+ zero h1pre) ----
__global__ __launch_bounds__(256) void pool_kernel(const float4* __restrict__ x,
                                                   int nb) {
    int gid = blockIdx.x * 256 + threadIdx.x;
    if (gid < C2 * BB / 4) ((float4*)d_h1pre)[gid] = make_float4(0.f, 0.f, 0.f, 0.f);
    int warp = gid >> 5;
    int lane = threadIdx.x & 31;
    for (int r = warp; r < BB * CC; r += nb * 8) {
        const float4* p = x + (size_t)r * 256 + lane;
        float s = 0.f;
#pragma unroll
        for (int k = 0; k < 8; k++) {
            float4 v = p[32 * k];
            s += (v.x + v.y) + (v.z + v.w);
        }
#pragma unroll
        for (int o = 16; o; o >>= 1) s += __shfl_xor_sync(0xffffffffu, s, o);
        if (lane == 0) {
            int b = r / CC, c = r - b * CC;
            d_gT[c * BB + b] = s * (1.0f / 1024.0f);
        }
    }
}

// packed-FMA GEMM body over a KC chunk, thread tile 4b x TJ j, w pitch KC+4
template<int TJ, int KC>
__device__ __forceinline__ void mm_body(const float* sa, const float* sw,
                                        int bg, int jg,
                                        unsigned long long* acc) {
    const float* aw = sw + (jg * TJ) * (KC + 4);
#pragma unroll 4
    for (int k4 = 0; k4 < KC / 4; k4++) {
        float4 wv[TJ];
#pragma unroll
        for (int q = 0; q < TJ; q++)
            wv[q] = *(const float4*)(aw + q * (KC + 4) + k4 * 4);
#pragma unroll
        for (int u = 0; u < 4; u++) {
            ulonglong2 av =
                *(const ulonglong2*)(sa + (k4 * 4 + u) * BB + bg * 4);
#pragma unroll
            for (int q = 0; q < TJ; q++) {
                float w = (u == 0) ? wv[q].x : (u == 1) ? wv[q].y
                        : (u == 2) ? wv[q].z : wv[q].w;
                unsigned long long ww;
                asm("mov.b64 %0, {%1, %1};" : "=l"(ww) : "f"(w));
                asm("fma.rn.f32x2 %0, %1, %2, %0;"
                    : "+l"(acc[q * 2 + 0]) : "l"(av.x), "l"(ww));
                asm("fma.rn.f32x2 %0, %1, %2, %0;"
                    : "+l"(acc[q * 2 + 1]) : "l"(av.y), "l"(ww));
            }
        }
    }
}

// ---- K1: gemm1, RED into h1pre. grid 288 = 24 jt (JT=64) x 12 ks (KC=64) ----
__global__ __launch_bounds__(256) void gemm1_kernel(const float* __restrict__ w1) {
    __shared__ float s_act[64 * BB];    // 16 KB
    __shared__ float s_w[64 * 68];      // 17 KB
    const int tid = threadIdx.x;
    const int bid = blockIdx.x;
    if (bid < 6) ((float4*)d_apre)[bid * 256 + tid] = make_float4(0.f, 0.f, 0.f, 0.f);
    int jt = bid % 24, ks = bid / 24;
    int j0 = jt * 64, k0 = ks * 64;
    const int bg = tid % 16, jg = tid / 16;
    {
        const float4* a4 = (const float4*)(d_gT + k0 * BB);
#pragma unroll
        for (int i = 0; i < 4; i++) ((float4*)s_act)[tid + 256 * i] = a4[tid + 256 * i];
        for (int f = tid; f < 64 * 16; f += 256) {
            int j = f >> 4, kq = f & 15;
            float4 v = *(const float4*)(w1 + (size_t)(j0 + j) * CC + k0 + kq * 4);
            *(float4*)(s_w + j * 68 + kq * 4) = v;
        }
    }
    __syncthreads();
    unsigned long long acc[8] = {};
    mm_body<4, 64>(s_act, s_w, bg, jg, acc);
#pragma unroll
    for (int q = 0; q < 4; q++) {
        int j = j0 + jg * 4 + q;
        red_add4(d_h1pre + j * BB + bg * 4, unpack2(acc[q * 2], acc[q * 2 + 1]));
    }
}

// ---- K2: ca1, BN+GELU applied on act fill, RED into apre ----
// grid 144 = 3 jt (JT=32) x 48 ks (KC=32). Also zeroes h3pre.
__global__ __launch_bounds__(256) void ca1_kernel(
    const float* __restrict__ caw1, const float* __restrict__ b1,
    const float* __restrict__ g1, const float* __restrict__ bt1,
    const float* __restrict__ m1, const float* __restrict__ v1) {
    __shared__ float s_act[32 * BB];    // 8 KB
    __shared__ float s_w[32 * 36];
    __shared__ float s_sc[32], s_sh[32];
    const int tid = threadIdx.x;
    const int bid = blockIdx.x;
    for (int i = bid * 256 + tid; i < CC * BB / 4; i += 144 * 256)
        ((float4*)d_h3pre)[i] = make_float4(0.f, 0.f, 0.f, 0.f);
    int jt = bid % 3, ks = bid / 3;
    int j0 = jt * 32, k0 = ks * 32;
    const int bg = tid % 16, jg = tid / 16;
    if (tid < 32) {
        int j = k0 + tid;
        float sc = rsqrtf(v1[j] + 1e-5f) * g1[j];
        s_sc[tid] = sc;
        s_sh[tid] = bt1[j] + (b1[j] - m1[j]) * sc;
    }
    __syncthreads();
    {
#pragma unroll
        for (int m = 0; m < 2; m++) {
            int i = tid + 256 * m;              // float4 index in 32x64 chunk
            int row = i >> 4;
            float4 v = ((const float4*)(d_h1pre + k0 * BB))[i];
            float sc = s_sc[row], sh = s_sh[row];
            v.x = gelu_exact(v.x * sc + sh);
            v.y = gelu_exact(v.y * sc + sh);
            v.z = gelu_exact(v.z * sc + sh);
            v.w = gelu_exact(v.w * sc + sh);
            ((float4*)s_act)[i] = v;
        }
        int f = tid;                            // 256 = 32*8 weight float4s
        int j = f >> 3, kq = f & 7;
        float4 v = *(const float4*)(caw1 + (size_t)(j0 + j) * C2 + k0 + kq * 4);
        *(float4*)(s_w + j * 36 + kq * 4) = v;
    }
    __syncthreads();
    unsigned long long acc[4] = {};
    mm_body<2, 32>(s_act, s_w, bg, jg, acc);
#pragma unroll
    for (int q = 0; q < 2; q++) {
        int j = j0 + jg * 2 + q;
        red_add4(d_apre + j * BB + bg * 4, unpack2(acc[q * 2], acc[q * 2 + 1]));
    }
}

// ---- K3: ca2 (K=96) with GELU-on-fill; gate vs recomputed h1T -> h2T ----
// grid 96 (JT=16)
__global__ __launch_bounds__(256) void ca2_kernel(
    const float* __restrict__ cab1,
    const float* __restrict__ caw2, const float* __restrict__ cab2,
    const float* __restrict__ b1,
    const float* __restrict__ g1, const float* __restrict__ bt1,
    const float* __restrict__ m1, const float* __restrict__ v1) {
    __shared__ float s_act[96 * BB];    // 24 KB
    __shared__ float s_w[16 * 100];
    const int tid = threadIdx.x;
    const int j0 = blockIdx.x * 16;
    const int bg = tid % 16, jg = tid / 16;
    {
#pragma unroll
        for (int m = 0; m < 6; m++) {
            int i = tid + 256 * m;              // 1536 float4 total
            int row = i >> 4;
            float bs = cab1[row];
            float4 v = ((const float4*)d_apre)[i];
            v.x = gelu_exact(v.x + bs);
            v.y = gelu_exact(v.y + bs);
            v.z = gelu_exact(v.z + bs);
            v.w = gelu_exact(v.w + bs);
            ((float4*)s_act)[i] = v;
        }
        for (int f = tid; f < 16 * 24; f += 256) {
            int j = f / 24, kq = f % 24;
            float4 v = ((const float4*)caw2)[(size_t)(j0 + j) * 24 + kq];
            *(float4*)(s_w + j * 100 + kq * 4) = v;
        }
    }
    __syncthreads();
    unsigned long long acc[2] = {};
    const float* aw = s_w + jg * 100;
#pragma unroll 4
    for (int k = 0; k < 96; k++) {
        ulonglong2 av = *(const ulonglong2*)(s_act + k * BB + bg * 4);
        float w = aw[k];
        unsigned long long ww;
        asm("mov.b64 %0, {%1, %1};" : "=l"(ww) : "f"(w));
        asm("fma.rn.f32x2 %0, %1, %2, %0;" : "+l"(acc[0]) : "l"(av.x), "l"(ww));
        asm("fma.rn.f32x2 %0, %1, %2, %0;" : "+l"(acc[1]) : "l"(av.y), "l"(ww));
    }
    int j = j0 + jg;
    float bias = cab2[j];
    float4 z = unpack2(acc[0], acc[1]);
    // recompute h1T[j][bg*4..] = GELU(BN(h1pre))
    float sc = rsqrtf(v1[j] + 1e-5f) * g1[j];
    float sh = bt1[j] + (b1[j] - m1[j]) * sc;
    float4 h = *(const float4*)(d_h1pre + j * BB + bg * 4);
    h.x = gelu_exact(h.x * sc + sh);
    h.y = gelu_exact(h.y * sc + sh);
    h.z = gelu_exact(h.z * sc + sh);
    h.w = gelu_exact(h.w * sc + sh);
    float4 o;
    o.x = h.x * sig2(z.x + bias);
    o.y = h.y * sig2(z.y + bias);
    o.z = h.z * sig2(z.z + bias);
    o.w = h.w * sig2(z.w + bias);
    *(float4*)(d_h2T + j * BB + bg * 4) = o;
}

// ---- K4: gemm2, RED into h3pre. grid 288 = 12 jt (JT=64) x 24 ks (KC=64) ----
__global__ __launch_bounds__(256) void gemm2_kernel(const float* __restrict__ w2) {
    __shared__ float s_act[64 * BB];
    __shared__ float s_w[64 * 68];
    const int tid = threadIdx.x;
    int jt = blockIdx.x % 12, ks = blockIdx.x / 12;
    int j0 = jt * 64, k0 = ks * 64;
    const int bg = tid % 16, jg = tid / 16;
    {
        const float4* a4 = (const float4*)(d_h2T + k0 * BB);
#pragma unroll
        for (int i = 0; i < 4; i++) ((float4*)s_act)[tid + 256 * i] = a4[tid + 256 * i];
        for (int f = tid; f < 64 * 16; f += 256) {
            int j = f >> 4, kq = f & 15;
            float4 v = *(const float4*)(w2 + (size_t)(j0 + j) * C2 + k0 + kq * 4);
            *(float4*)(s_w + j * 68 + kq * 4) = v;
        }
    }
    __syncthreads();
    unsigned long long acc[8] = {};
    mm_body<4, 64>(s_act, s_w, bg, jg, acc);
#pragma unroll
    for (int q = 0; q < 4; q++) {
        int j = j0 + jg * 4 + q;
        red_add4(d_h3pre + j * BB + bg * 4, unpack2(acc[q * 2], acc[q * 2 + 1]));
    }
}

// ---- K5: BN+GELU(h3pre) + scores + top-2 + softmax. grid 64 x 512 ----
__global__ __launch_bounds__(512) void scores_kernel(
    const float* __restrict__ b2,
    const float* __restrict__ g2, const float* __restrict__ bt2,
    const float* __restrict__ m2, const float* __restrict__ v2,
    const float* __restrict__ w3, const float* __restrict__ b3,
    float* __restrict__ out) {
    __shared__ float h3s[CC];
    __shared__ float sc[EE];
    const int tid = threadIdx.x;
    const int b = blockIdx.x;
    for (int j = tid; j < CC; j += 512) {
        float v = d_h3pre[j * BB + b];
        float scale = rsqrtf(v2[j] + 1e-5f) * g2[j];
        float shift = bt2[j] + (b2[j] - m2[j]) * scale;
        h3s[j] = gelu_exact(v * scale + shift);
    }
    __syncthreads();
    int e = tid >> 5, lane = tid & 31;
    const float* wr = w3 + e * CC;
    float s = 0.f;
#pragma unroll
    for (int i = 0; i < CC / 32; i++) {
        int k = lane + 32 * i;
        s = fmaf(h3s[k], wr[k], s);
    }
#pragma unroll
    for (int o = 16; o; o >>= 1) s += __shfl_xor_sync(0xffffffffu, s, o);
    if (lane == 0) sc[e] = s + b3[e];
    __syncthreads();
    if (tid == 0) {
        int i0 = 0; float v0 = sc[0];
#pragma unroll
        for (int t = 1; t < EE; t++) { if (sc[t] > v0) { v0 = sc[t]; i0 = t; } }
        int i1 = -1; float v1 = -3.402823466e38f;
#pragma unroll
        for (int t = 0; t < EE; t++) {
            if (t != i0 && sc[t] > v1) { v1 = sc[t]; i1 = t; }
        }
        float e1  = expf((v1 - v0) * 0.5f);
        float inv = 1.0f / (1.0f + e1);
        out[b * 2 + 0]       = (float)i0;
        out[b * 2 + 1]       = (float)i1;
        out[128 + b * 2 + 0] = inv;
        out[128 + b * 2 + 1] = e1 * inv;
    }
}

extern "C" void kernel_launch(void* const* d_in, const int* in_sizes, int n_in,
                              void* d_out, int out_size) {
    const float* x     = (const float*)d_in[0];
    const float* w1    = (const float*)d_in[1];
    const float* b1    = (const float*)d_in[2];
    const float* bn1_g = (const float*)d_in[3];
    const float* bn1_b = (const float*)d_in[4];
    const float* bn1_m = (const float*)d_in[5];
    const float* bn1_v = (const float*)d_in[6];
    const float* caw1  = (const float*)d_in[7];
    const float* cab1  = (const float*)d_in[8];
    const float* caw2  = (const float*)d_in[9];
    const float* cab2  = (const float*)d_in[10];
    const float* w2    = (const float*)d_in[11];
    const float* b2    = (const float*)d_in[12];
    const float* bn2_g = (const float*)d_in[13];
    const float* bn2_b = (const float*)d_in[14];
    const float* bn2_m = (const float*)d_in[15];
    const float* bn2_v = (const float*)d_in[16];
    const float* w3    = (const float*)d_in[17];
    const float* b3    = (const float*)d_in[18];

    int nsm = 148;
    cudaDeviceGetAttribute(&nsm, cudaDevAttrMultiProcessorCount, 0);
    int nb = 4 * nsm;

    pool_kernel<<<nb, 256>>>((const float4*)x, nb);
    gemm1_kernel<<<288, 256>>>(w1);
    ca1_kernel<<<144, 256>>>(caw1, b1, bn1_g, bn1_b, bn1_m, bn1_v);
    ca2_kernel<<<96, 256>>>(cab1, caw2, cab2, b1, bn1_g, bn1_b, bn1_m, bn1_v);
    gemm2_kernel<<<288, 256>>>(w2);
    scores_kernel<<<64, 512>>>(b2, bn2_g, bn2_b, bn2_m, bn2_v, w3, b3,
                               (float*)d_out);
}